// round 10
// baseline (speedup 1.0000x reference)
#include <cuda_runtime.h>

#define BB 4096
#define TT 200
#define DD 128
#define KS 5
#define NTHREADS 256
#define RPB 2                    // batch rows per CTA
#define STG_T 40                 // tokens staged in smem per row

#define CB_ROWS 32
#define WV_P4 33
#define CB_SMEM ((DD * WV_P4 * 4 + CB_ROWS * DD) * 4)

// dynamic smem layout (float offsets)
#define OFF_STAGE 0                       // 2*40*128 = 10240
#define OFF_MASK  10240                   // 2*200
#define OFF_AGE   10640                   // 2*200
#define OFF_POP   11040                   // 2*200
#define OFF_DLOG  11440                   // 2*200
#define OFF_MEAN  11840                   // 2*128
#define OFF_Q     12096                   // 2*128
#define OFF_R     12352                   // 2*128
#define OFF_PART  12608                   // 1024
#define OFF_WM    13632                   // 8
#define OFF_WZ    13640                   // 8
#define OFF_SCAL  13648                   // 4
#define UE_SMEM   ((13652) * 4)

__device__ float g_w[BB * DD];    // normalized attention-weighted sum
__device__ float g_us[BB * DD];   // g * short_term
__device__ float g_omg[BB];       // 1 - g

__device__ __forceinline__ float warp_sum(float v) {
#pragma unroll
    for (int o = 16; o; o >>= 1) v += __shfl_xor_sync(0xffffffffu, v, o);
    return v;
}

__global__ void __launch_bounds__(NTHREADS, 4)
user_enc_kernel(const float* __restrict__ items_g,
                const int* __restrict__ mask_g,
                const float* __restrict__ age_g,
                const float* __restrict__ pop_g,
                const float* __restrict__ Wq,
                const float* __restrict__ Wk,
                const float* __restrict__ gate_w,
                const float* __restrict__ gate_b,
                const float* __restrict__ dalpha) {
    extern __shared__ float sm[];
    float4* stg4  = (float4*)(sm + OFF_STAGE);
    float* s_mask = sm + OFF_MASK;
    float* s_age  = sm + OFF_AGE;
    float* s_pop  = sm + OFF_POP;
    float* s_dlog = sm + OFF_DLOG;
    float* s_mean = sm + OFF_MEAN;
    float* s_q    = sm + OFF_Q;
    float* s_r    = sm + OFF_R;
    float* s_part = sm + OFF_PART;
    float* s_wm   = sm + OFF_WM;
    float* s_wz   = sm + OFF_WZ;
    float* s_scal = sm + OFF_SCAL;

    const int tid  = threadIdx.x;
    const int lane = tid & 31;
    const int warp = tid >> 5;
    const int b0   = blockIdx.x * RPB;
    const float NEG_INF = __int_as_float(0xff800000);

    // ---- phase 0: metadata + decay-log for both rows ----
    const float alpha = log1pf(expf(dalpha[0])) + 1e-6f;
#pragma unroll
    for (int r = 0; r < RPB; ++r) {
        if (tid < TT) {
            int m = mask_g[(size_t)(b0 + r) * TT + tid];
            float a = age_g[(size_t)(b0 + r) * TT + tid];
            s_mask[r * TT + tid] = m ? 1.f : 0.f;
            s_age[r * TT + tid]  = a;
            s_pop[r * TT + tid]  = pop_g[(size_t)(b0 + r) * TT + tid];
            s_dlog[r * TT + tid] = m ? __logf(__expf(-alpha * a) + 1e-12f) : NEG_INF;
        }
    }
    __syncthreads();

    // ---- pass 1 (DRAM): masked mean + stage first 40 tokens, per row ----
#pragma unroll
    for (int r = 0; r < RPB; ++r) {
        const float4* row4 = (const float4*)(items_g + (size_t)(b0 + r) * TT * DD);
        float4 acc = make_float4(0.f, 0.f, 0.f, 0.f);
#pragma unroll
        for (int k = 0; k < (TT * DD / 4) / NTHREADS; ++k) {  // 25
            int i = tid + k * NTHREADS;
            float4 v = row4[i];
            if (k < (STG_T * DD / 4) / NTHREADS)   // k<5 -> t<40
                stg4[r * (STG_T * 32) + i] = v;
            float m = s_mask[r * TT + (i >> 5)];
            acc.x += m * v.x; acc.y += m * v.y; acc.z += m * v.z; acc.w += m * v.w;
        }
        ((float4*)s_part)[tid] = acc;
        if (warp == 0) {
            float c = 0.f;
            for (int t = lane; t < TT; t += 32) c += s_mask[r * TT + t];
            c = warp_sum(c);
            if (lane == 0) s_scal[r] = c;
        }
        __syncthreads();
        if (tid < DD) {
            int d4 = tid >> 2, comp = tid & 3;
            float s = 0.f;
#pragma unroll
            for (int j = 0; j < 8; ++j)
                s += s_part[(j * 32 + d4) * 4 + comp];
            s_mean[r * DD + tid] = s / (s_scal[r] + 1e-6f);
        }
        __syncthreads();
    }

    // ---- q phase: one Wq pass serves both rows ----
    {
        float4 mv0 = ((const float4*)(s_mean))[lane];
        float4 mv1 = ((const float4*)(s_mean + DD))[lane];
#pragma unroll
        for (int k = 0; k < 16; ++k) {
            int i = warp + k * 8;
            float4 w4 = ((const float4*)(Wq + (size_t)i * DD))[lane];
            float d0 = w4.x * mv0.x + w4.y * mv0.y + w4.z * mv0.z + w4.w * mv0.w;
            float d1 = w4.x * mv1.x + w4.y * mv1.y + w4.z * mv1.z + w4.w * mv1.w;
            d0 = warp_sum(d0);
            d1 = warp_sum(d1);
            if (lane == 0) { s_q[i] = d0; s_q[DD + i] = d1; }
        }
    }
    __syncthreads();

    // ---- r phase: one Wk pass serves both rows ----
    {
        int e = tid & 127, half = tid >> 7;
        const float* Kp  = Wk + (size_t)half * 64 * DD + e;
        const float* qp0 = s_q + half * 64;
        const float* qp1 = s_q + DD + half * 64;
        float r0 = 0.f, r1 = 0.f;
#pragma unroll 16
        for (int i = 0; i < 64; ++i) {
            float v = Kp[(size_t)i * DD];
            r0 += qp0[i] * v;
            r1 += qp1[i] * v;
        }
        s_part[half * DD + e]       = r0;
        s_part[512 + half * DD + e] = r1;
    }
    __syncthreads();
    if (tid < DD) {
        s_r[tid]      = s_part[tid] + s_part[DD + tid];
        s_r[DD + tid] = s_part[512 + tid] + s_part[512 + DD + tid];
    }
    __syncthreads();

    // ---- pass 2 + merge + epilogue, per row (registers reused) ----
    const float scale = 0.08838834764831845f;  // 1/sqrt(128)
#pragma unroll
    for (int r = 0; r < RPB; ++r) {
        const float4* row4 = (const float4*)(items_g + (size_t)(b0 + r) * TT * DD);
        {
            float4 rv = ((const float4*)(s_r + r * DD))[lane];
            float m = NEG_INF, Z = 0.f;
            float4 acc = make_float4(0.f, 0.f, 0.f, 0.f);
#pragma unroll
            for (int kb = 0; kb < 5; ++kb) {
                float4 xv[5];
                float  dt[5];
#pragma unroll
                for (int j = 0; j < 5; ++j) {
                    int t = warp + (kb * 5 + j) * 8;
                    xv[j] = (kb == 0) ? stg4[r * (STG_T * 32) + t * 32 + lane]
                                      : row4[t * 32 + lane];
                }
#pragma unroll
                for (int j = 0; j < 5; ++j) {
                    float d = xv[j].x * rv.x + xv[j].y * rv.y +
                              xv[j].z * rv.z + xv[j].w * rv.w;
                    dt[j] = warp_sum(d);
                }
#pragma unroll
                for (int j = 0; j < 5; ++j) {
                    int t = warp + (kb * 5 + j) * 8;
                    float dl = s_dlog[r * TT + t];
                    if (dl != NEG_INF) {
                        float s = dt[j] * scale + dl;
                        if (s > m) {
                            float c = __expf(m - s);
                            Z *= c;
                            acc.x *= c; acc.y *= c; acc.z *= c; acc.w *= c;
                            m = s;
                        }
                        float p = __expf(s - m);
                        Z += p;
                        acc.x += p * xv[j].x; acc.y += p * xv[j].y;
                        acc.z += p * xv[j].z; acc.w += p * xv[j].w;
                    }
                }
            }
            ((float4*)s_part)[warp * 32 + lane] = acc;
            if (lane == 0) { s_wm[warp] = m; s_wz[warp] = Z; }
        }
        __syncthreads();

        if (tid < DD) {
            // merge warp softmax states -> normalized w
            float M = s_wm[0];
#pragma unroll
            for (int j = 1; j < 8; ++j) M = fmaxf(M, s_wm[j]);
            float Zt = 0.f, w = 0.f;
#pragma unroll
            for (int j = 0; j < 8; ++j) {
                float f = __expf(s_wm[j] - M);
                Zt += f * s_wz[j];
                w  += f * s_part[j * DD + tid];
            }
            g_w[(size_t)(b0 + r) * DD + tid] = w / Zt;

            // short-term window, gate
            const float* rowp = items_g + (size_t)(b0 + r) * TT * DD;
            int cnt = (int)(s_scal[r] + 0.5f);
            if (cnt < 1) cnt = 1;
            int start = cnt - KS;
            if (start < 0) start = 0;
            float dn = (float)(cnt - start);

            float st = 0.f;
            if (cnt <= STG_T) {
                const float* sp = sm + OFF_STAGE + r * (STG_T * DD);
                for (int t = start; t < cnt; ++t) st += sp[t * DD + tid];
            } else {
                for (int t = start; t < cnt; ++t) st += rowp[t * DD + tid];
            }
            st /= dn;

            float mp = 0.f, mr = 0.f;
            for (int t = start; t < cnt; ++t) {
                mp += s_pop[r * TT + t]; mr += s_age[r * TT + t];
            }
            mp /= dn; mr /= dn;

            float z = mp * gate_w[0] + mr * gate_w[1] + gate_b[0];
            float g = 1.f / (1.f + __expf(-z));
            g_us[(size_t)(b0 + r) * DD + tid] = g * st;
            if (tid == 0) g_omg[b0 + r] = 1.f - g;
        }
        __syncthreads();
    }
}

// combine: LT = w @ Wv^T, full Wv staged once (float4-padded), float4 LDS GEMM,
// then user = g_us + (1-g)*LT, LayerNorm, out. Grid 128 x 32 rows.
__global__ void __launch_bounds__(NTHREADS, 1)
combine_kernel(const float* __restrict__ Wv,
               const float* __restrict__ ln_g,
               const float* __restrict__ ln_b,
               float* __restrict__ out) {
    extern __shared__ float cs[];
    float4* wv4 = (float4*)cs;                     // [DD][WV_P4] float4s
    float*  w_s = cs + DD * WV_P4 * 4;             // [CB_ROWS][DD], reused for LT
    float4* w4s = (float4*)w_s;

    const int tid  = threadIdx.x;
    const int lane = tid & 31;
    const int warp = tid >> 5;
    const int row0 = blockIdx.x * CB_ROWS;
    const int r0 = warp * 4;

#pragma unroll
    for (int k = 0; k < 16; ++k) {
        int i = tid + k * NTHREADS;
        int e = i >> 5, d4 = i & 31;
        wv4[e * WV_P4 + d4] = ((const float4*)Wv)[i];
    }
#pragma unroll
    for (int k = 0; k < 4; ++k) {
        int i = tid + k * NTHREADS;
        w4s[i] = ((const float4*)(g_w + (size_t)row0 * DD))[i];
    }
    __syncthreads();

    float acc[4][4] = {};
#pragma unroll 4
    for (int d4 = 0; d4 < 32; ++d4) {
        float4 wr[4], vv[4];
#pragma unroll
        for (int i = 0; i < 4; ++i) wr[i] = w4s[(r0 + i) * 32 + d4];
#pragma unroll
        for (int j = 0; j < 4; ++j) vv[j] = wv4[(lane + 32 * j) * WV_P4 + d4];
#pragma unroll
        for (int i = 0; i < 4; ++i)
#pragma unroll
            for (int j = 0; j < 4; ++j)
                acc[i][j] += wr[i].x * vv[j].x + wr[i].y * vv[j].y +
                             wr[i].z * vv[j].z + wr[i].w * vv[j].w;
    }
    __syncthreads();
#pragma unroll
    for (int i = 0; i < 4; ++i)
#pragma unroll
        for (int j = 0; j < 4; ++j)
            w_s[(r0 + i) * DD + lane + 32 * j] = acc[i][j];
    __syncthreads();

    const float4 lg4 = ((const float4*)ln_g)[lane];
    const float4 lb4 = ((const float4*)ln_b)[lane];
#pragma unroll
    for (int i = 0; i < 4; ++i) {
        int rr = warp * 4 + i;
        int grow = row0 + rr;
        float4 lt4 = ((const float4*)(w_s + rr * DD))[lane];
        float4 us4 = ((const float4*)(g_us + (size_t)grow * DD))[lane];
        float om = g_omg[grow];
        float4 u;
        u.x = us4.x + om * lt4.x; u.y = us4.y + om * lt4.y;
        u.z = us4.z + om * lt4.z; u.w = us4.w + om * lt4.w;
        float mu = warp_sum(u.x + u.y + u.z + u.w) * (1.f / 128.f);
        float dx = u.x - mu, dy = u.y - mu, dz = u.z - mu, dw = u.w - mu;
        float var = warp_sum(dx * dx + dy * dy + dz * dz + dw * dw) * (1.f / 128.f);
        float rs = rsqrtf(var + 1e-5f);
        float4 o;
        o.x = dx * rs * lg4.x + lb4.x; o.y = dy * rs * lg4.y + lb4.y;
        o.z = dz * rs * lg4.z + lb4.z; o.w = dw * rs * lg4.w + lb4.w;
        ((float4*)(out + (size_t)grow * DD))[lane] = o;
    }
}

extern "C" void kernel_launch(void* const* d_in, const int* in_sizes, int n_in,
                              void* d_out, int out_size) {
    const float* items = (const float*)d_in[0];
    const int*   mask  = (const int*)d_in[1];
    const float* age   = (const float*)d_in[2];
    const float* pop   = (const float*)d_in[3];
    const float* Wq    = (const float*)d_in[4];
    const float* Wk    = (const float*)d_in[5];
    const float* Wv    = (const float*)d_in[6];
    const float* gw    = (const float*)d_in[7];
    const float* gb    = (const float*)d_in[8];
    const float* lng   = (const float*)d_in[9];
    const float* lnb   = (const float*)d_in[10];
    const float* da    = (const float*)d_in[11];
    float* out = (float*)d_out;

    cudaFuncSetAttribute(user_enc_kernel,
                         cudaFuncAttributeMaxDynamicSharedMemorySize, UE_SMEM);
    user_enc_kernel<<<BB / RPB, NTHREADS, UE_SMEM>>>(items, mask, age, pop,
                                                     Wq, Wk, gw, gb, da);
    cudaFuncSetAttribute(combine_kernel,
                         cudaFuncAttributeMaxDynamicSharedMemorySize, CB_SMEM);
    combine_kernel<<<BB / CB_ROWS, NTHREADS, CB_SMEM>>>(Wv, lng, lnb, out);
}

// round 11
// speedup vs baseline: 1.1716x; 1.1716x over previous
#include <cuda_runtime.h>

#define BB 4096
#define TT 200
#define DD 128
#define KS 5
#define NTHREADS 256

#define CB_ROWS 32
#define CB_THREADS 512
#define WV_P4 33
#define CB_SMEM ((DD * WV_P4 * 4 + CB_ROWS * DD) * 4)

__device__ float g_w[BB * DD];    // normalized attention-weighted sum
__device__ float g_us[BB * DD];   // g * short_term
__device__ float g_omg[BB];       // 1 - g

__device__ __forceinline__ float warp_sum(float v) {
#pragma unroll
    for (int o = 16; o; o >>= 1) v += __shfl_xor_sync(0xffffffffu, v, o);
    return v;
}

__global__ void __launch_bounds__(NTHREADS, 5)
user_enc_kernel(const float* __restrict__ items_g,
                const int* __restrict__ mask_g,
                const float* __restrict__ age_g,
                const float* __restrict__ pop_g,
                const float* __restrict__ Wq,
                const float* __restrict__ Wk,
                const float* __restrict__ gate_w,
                const float* __restrict__ gate_b,
                const float* __restrict__ dalpha) {
    __shared__ float s_mask[TT];
    __shared__ float s_age[TT];
    __shared__ float s_pop[TT];
    __shared__ float s_dlog[TT];
    __shared__ float s_mean[DD];
    __shared__ float s_q[DD];
    __shared__ float s_r[DD];
    __shared__ float s_part[1024];
    __shared__ float s_wm[8];
    __shared__ float s_wz[8];
    __shared__ float s_scal[4];

    const int tid  = threadIdx.x;
    const int lane = tid & 31;
    const int warp = tid >> 5;
    const int b    = blockIdx.x;
    const float NEG_INF = __int_as_float(0xff800000);
    const float* row = items_g + (size_t)b * TT * DD;
    const float4* row4 = (const float4*)row;

    // ---- phase 0: metadata + decay-log (parallel) ----
    const float alpha = log1pf(expf(dalpha[0])) + 1e-6f;
    if (tid < TT) {
        int m = mask_g[(size_t)b * TT + tid];
        float a = age_g[(size_t)b * TT + tid];
        s_mask[tid] = m ? 1.f : 0.f;
        s_age[tid]  = a;
        s_pop[tid]  = pop_g[(size_t)b * TT + tid];
        s_dlog[tid] = m ? __logf(__expf(-alpha * a) + 1e-12f) : NEG_INF;
    }
    __syncthreads();

    // ---- pass 1 (DRAM): masked mean accumulation ----
    {
        float4 acc = make_float4(0.f, 0.f, 0.f, 0.f);
#pragma unroll
        for (int k = 0; k < (TT * DD / 4) / NTHREADS; ++k) {  // 25
            int i = tid + k * NTHREADS;
            float4 v = row4[i];
            float m = s_mask[i >> 5];
            acc.x += m * v.x; acc.y += m * v.y; acc.z += m * v.z; acc.w += m * v.w;
        }
        ((float4*)s_part)[tid] = acc;
        if (warp == 0) {
            float c = 0.f;
            for (int t = lane; t < TT; t += 32) c += s_mask[t];
            c = warp_sum(c);
            if (lane == 0) s_scal[0] = c;
        }
    }
    __syncthreads();
    const float cntf = s_scal[0];

    if (tid < DD) {
        int d4 = tid >> 2, comp = tid & 3;
        float s = 0.f;
#pragma unroll
        for (int j = 0; j < 8; ++j)
            s += s_part[(j * 32 + d4) * 4 + comp];
        s_mean[tid] = s / (cntf + 1e-6f);
    }
    __syncthreads();

    // ---- q[i] = dot(Wq row i, mean): warp-per-i, coalesced ----
    {
        float4 mv = ((const float4*)s_mean)[lane];
#pragma unroll
        for (int k = 0; k < 16; ++k) {
            int i = warp + k * 8;
            float4 w4 = ((const float4*)(Wq + (size_t)i * DD))[lane];
            float d = w4.x * mv.x + w4.y * mv.y + w4.z * mv.z + w4.w * mv.w;
            d = warp_sum(d);
            if (lane == 0) s_q[i] = d;
        }
    }
    __syncthreads();

    // ---- r[d] = sum_i q[i]*Wk[i,d], i split over halves, coalesced ----
    {
        int e = tid & 127, half = tid >> 7;
        const float* Kp = Wk + (size_t)half * 64 * DD + e;
        const float* qp = s_q + half * 64;
        float r = 0.f;
#pragma unroll 16
        for (int i = 0; i < 64; ++i)
            r += qp[i] * Kp[(size_t)i * DD];
        s_part[half * DD + e] = r;
    }
    __syncthreads();
    if (tid < DD) s_r[tid] = s_part[tid] + s_part[DD + tid];
    __syncthreads();

    // ---- pass 2 (L2): fused scores + online softmax + weighted sum ----
    const float scale = 0.08838834764831845f;  // 1/sqrt(128)
    {
        float4 rv = ((const float4*)s_r)[lane];
        float m = NEG_INF, Z = 0.f;
        float4 acc = make_float4(0.f, 0.f, 0.f, 0.f);
#pragma unroll
        for (int kb = 0; kb < 5; ++kb) {
            float4 xv[5];
            float  dt[5];
#pragma unroll
            for (int j = 0; j < 5; ++j) {
                int t = warp + (kb * 5 + j) * 8;
                xv[j] = row4[t * 32 + lane];
            }
#pragma unroll
            for (int j = 0; j < 5; ++j) {
                float d = xv[j].x * rv.x + xv[j].y * rv.y +
                          xv[j].z * rv.z + xv[j].w * rv.w;
                dt[j] = warp_sum(d);
            }
#pragma unroll
            for (int j = 0; j < 5; ++j) {
                int t = warp + (kb * 5 + j) * 8;
                float dl = s_dlog[t];
                if (dl != NEG_INF) {
                    float s = dt[j] * scale + dl;
                    if (s > m) {
                        float c = __expf(m - s);
                        Z *= c;
                        acc.x *= c; acc.y *= c; acc.z *= c; acc.w *= c;
                        m = s;
                    }
                    float p = __expf(s - m);
                    Z += p;
                    acc.x += p * xv[j].x; acc.y += p * xv[j].y;
                    acc.z += p * xv[j].z; acc.w += p * xv[j].w;
                }
            }
        }
        ((float4*)s_part)[warp * 32 + lane] = acc;
        if (lane == 0) { s_wm[warp] = m; s_wz[warp] = Z; }
    }
    __syncthreads();

    // ---- merge warp states, write normalized w to global scratch ----
    if (tid < DD) {
        float M = s_wm[0];
#pragma unroll
        for (int j = 1; j < 8; ++j) M = fmaxf(M, s_wm[j]);
        float Zt = 0.f, w = 0.f;
#pragma unroll
        for (int j = 0; j < 8; ++j) {
            float f = __expf(s_wm[j] - M);
            Zt += f * s_wz[j];
            w  += f * s_part[j * DD + tid];
        }
        g_w[(size_t)b * DD + tid] = w / Zt;
    }

    // ---- short-term window (L2-hot rows), gate; write pre-gated parts ----
    if (tid < DD) {
        int cnt = (int)(cntf + 0.5f);
        if (cnt < 1) cnt = 1;
        int start = cnt - KS;
        if (start < 0) start = 0;
        float dn = (float)(cnt - start);

        float st = 0.f;
        for (int t = start; t < cnt; ++t) st += row[t * DD + tid];
        st /= dn;

        float mp = 0.f, mr = 0.f;
        for (int t = start; t < cnt; ++t) { mp += s_pop[t]; mr += s_age[t]; }
        mp /= dn; mr /= dn;

        float z = mp * gate_w[0] + mr * gate_w[1] + gate_b[0];
        float g = 1.f / (1.f + __expf(-z));
        g_us[(size_t)b * DD + tid] = g * st;
        if (tid == 0) g_omg[b] = 1.f - g;
    }
}

// combine: LT = w @ Wv^T, full Wv staged once (float4-padded), float4 LDS GEMM,
// 512 threads (16 warps) for latency hiding. Then gate-combine + LN.
__global__ void __launch_bounds__(CB_THREADS, 1)
combine_kernel(const float* __restrict__ Wv,
               const float* __restrict__ ln_g,
               const float* __restrict__ ln_b,
               float* __restrict__ out) {
    extern __shared__ float cs[];
    float4* wv4 = (float4*)cs;                     // [DD][WV_P4] float4s
    float*  w_s = cs + DD * WV_P4 * 4;             // [CB_ROWS][DD], reused for LT
    float4* w4s = (float4*)w_s;

    const int tid  = threadIdx.x;
    const int lane = tid & 31;
    const int warp = tid >> 5;                     // 0..15
    const int row0 = blockIdx.x * CB_ROWS;
    const int r0 = warp * 2;                       // 2 rows per warp

    // stage Wv: 4096 float4 over 512 threads = 8 iters
#pragma unroll
    for (int k = 0; k < 8; ++k) {
        int i = tid + k * CB_THREADS;
        int e = i >> 5, d4 = i & 31;
        wv4[e * WV_P4 + d4] = ((const float4*)Wv)[i];
    }
    // load w rows (32x128 = 1024 float4) over 512 threads = 2 iters
#pragma unroll
    for (int k = 0; k < 2; ++k) {
        int i = tid + k * CB_THREADS;
        w4s[i] = ((const float4*)(g_w + (size_t)row0 * DD))[i];
    }
    __syncthreads();

    // GEMM: thread tile 2 rows x 4 e, float4 over d (32 iters)
    float acc[2][4] = {};
#pragma unroll 4
    for (int d4 = 0; d4 < 32; ++d4) {
        float4 wr[2], vv[4];
#pragma unroll
        for (int i = 0; i < 2; ++i) wr[i] = w4s[(r0 + i) * 32 + d4];
#pragma unroll
        for (int j = 0; j < 4; ++j) vv[j] = wv4[(lane + 32 * j) * WV_P4 + d4];
#pragma unroll
        for (int i = 0; i < 2; ++i)
#pragma unroll
            for (int j = 0; j < 4; ++j)
                acc[i][j] += wr[i].x * vv[j].x + wr[i].y * vv[j].y +
                             wr[i].z * vv[j].z + wr[i].w * vv[j].w;
    }
    __syncthreads();
    // store LT into w_s (w fully consumed)
#pragma unroll
    for (int i = 0; i < 2; ++i)
#pragma unroll
        for (int j = 0; j < 4; ++j)
            w_s[(r0 + i) * DD + lane + 32 * j] = acc[i][j];
    __syncthreads();

    // LN: 2 rows per warp
    const float4 lg4 = ((const float4*)ln_g)[lane];
    const float4 lb4 = ((const float4*)ln_b)[lane];
#pragma unroll
    for (int i = 0; i < 2; ++i) {
        int rr = r0 + i;
        int grow = row0 + rr;
        float4 lt4 = ((const float4*)(w_s + rr * DD))[lane];
        float4 us4 = ((const float4*)(g_us + (size_t)grow * DD))[lane];
        float om = g_omg[grow];
        float4 u;
        u.x = us4.x + om * lt4.x; u.y = us4.y + om * lt4.y;
        u.z = us4.z + om * lt4.z; u.w = us4.w + om * lt4.w;
        float mu = warp_sum(u.x + u.y + u.z + u.w) * (1.f / 128.f);
        float dx = u.x - mu, dy = u.y - mu, dz = u.z - mu, dw = u.w - mu;
        float var = warp_sum(dx * dx + dy * dy + dz * dz + dw * dw) * (1.f / 128.f);
        float rs = rsqrtf(var + 1e-5f);
        float4 o;
        o.x = dx * rs * lg4.x + lb4.x; o.y = dy * rs * lg4.y + lb4.y;
        o.z = dz * rs * lg4.z + lb4.z; o.w = dw * rs * lg4.w + lb4.w;
        ((float4*)(out + (size_t)grow * DD))[lane] = o;
    }
}

extern "C" void kernel_launch(void* const* d_in, const int* in_sizes, int n_in,
                              void* d_out, int out_size) {
    const float* items = (const float*)d_in[0];
    const int*   mask  = (const int*)d_in[1];
    const float* age   = (const float*)d_in[2];
    const float* pop   = (const float*)d_in[3];
    const float* Wq    = (const float*)d_in[4];
    const float* Wk    = (const float*)d_in[5];
    const float* Wv    = (const float*)d_in[6];
    const float* gw    = (const float*)d_in[7];
    const float* gb    = (const float*)d_in[8];
    const float* lng   = (const float*)d_in[9];
    const float* lnb   = (const float*)d_in[10];
    const float* da    = (const float*)d_in[11];
    float* out = (float*)d_out;

    user_enc_kernel<<<BB, NTHREADS>>>(items, mask, age, pop, Wq, Wk, gw, gb, da);
    cudaFuncSetAttribute(combine_kernel,
                         cudaFuncAttributeMaxDynamicSharedMemorySize, CB_SMEM);
    combine_kernel<<<BB / CB_ROWS, CB_THREADS, CB_SMEM>>>(Wv, lng, lnb, out);
}

// round 12
// speedup vs baseline: 1.1833x; 1.0100x over previous
#include <cuda_runtime.h>

#define BB 4096
#define TT 200
#define DD 128
#define KS 5
#define NTHREADS 256

#define CB_ROWS 16
#define CB_THREADS 256
#define WV_P4 33
#define CB_SMEM ((DD * WV_P4 * 4 + CB_ROWS * DD) * 4)

__device__ float g_w[BB * DD];    // normalized attention-weighted sum
__device__ float g_us[BB * DD];   // g * short_term
__device__ float g_omg[BB];       // 1 - g

__device__ __forceinline__ float warp_sum(float v) {
#pragma unroll
    for (int o = 16; o; o >>= 1) v += __shfl_xor_sync(0xffffffffu, v, o);
    return v;
}

__global__ void __launch_bounds__(NTHREADS, 5)
user_enc_kernel(const float* __restrict__ items_g,
                const int* __restrict__ mask_g,
                const float* __restrict__ age_g,
                const float* __restrict__ pop_g,
                const float* __restrict__ Wq,
                const float* __restrict__ Wk,
                const float* __restrict__ gate_w,
                const float* __restrict__ gate_b,
                const float* __restrict__ dalpha) {
    __shared__ float s_mask[TT];
    __shared__ float s_age[TT];
    __shared__ float s_pop[TT];
    __shared__ float s_dlog[TT];
    __shared__ float s_mean[DD];
    __shared__ float s_q[DD];
    __shared__ float s_r[DD];
    __shared__ float s_part[1024];
    __shared__ float s_wm[8];
    __shared__ float s_wz[8];
    __shared__ float s_scal[4];

    const int tid  = threadIdx.x;
    const int lane = tid & 31;
    const int warp = tid >> 5;
    const int b    = blockIdx.x;
    const float NEG_INF = __int_as_float(0xff800000);
    const float* row = items_g + (size_t)b * TT * DD;
    const float4* row4 = (const float4*)row;

    // ---- phase 0: metadata + decay-log (parallel) ----
    const float alpha = log1pf(expf(dalpha[0])) + 1e-6f;
    if (tid < TT) {
        int m = mask_g[(size_t)b * TT + tid];
        float a = age_g[(size_t)b * TT + tid];
        s_mask[tid] = m ? 1.f : 0.f;
        s_age[tid]  = a;
        s_pop[tid]  = pop_g[(size_t)b * TT + tid];
        s_dlog[tid] = m ? __logf(__expf(-alpha * a) + 1e-12f) : NEG_INF;
    }
    __syncthreads();

    // ---- pass 1 (DRAM): masked mean accumulation ----
    {
        float4 acc = make_float4(0.f, 0.f, 0.f, 0.f);
#pragma unroll
        for (int k = 0; k < (TT * DD / 4) / NTHREADS; ++k) {  // 25
            int i = tid + k * NTHREADS;
            float4 v = row4[i];
            float m = s_mask[i >> 5];
            acc.x += m * v.x; acc.y += m * v.y; acc.z += m * v.z; acc.w += m * v.w;
        }
        ((float4*)s_part)[tid] = acc;
        if (warp == 0) {
            float c = 0.f;
            for (int t = lane; t < TT; t += 32) c += s_mask[t];
            c = warp_sum(c);
            if (lane == 0) s_scal[0] = c;
        }
    }
    __syncthreads();
    const float cntf = s_scal[0];

    if (tid < DD) {
        int d4 = tid >> 2, comp = tid & 3;
        float s = 0.f;
#pragma unroll
        for (int j = 0; j < 8; ++j)
            s += s_part[(j * 32 + d4) * 4 + comp];
        s_mean[tid] = s / (cntf + 1e-6f);
    }
    __syncthreads();

    // ---- q[i] = dot(Wq row i, mean): warp-per-i, coalesced ----
    {
        float4 mv = ((const float4*)s_mean)[lane];
#pragma unroll
        for (int k = 0; k < 16; ++k) {
            int i = warp + k * 8;
            float4 w4 = ((const float4*)(Wq + (size_t)i * DD))[lane];
            float d = w4.x * mv.x + w4.y * mv.y + w4.z * mv.z + w4.w * mv.w;
            d = warp_sum(d);
            if (lane == 0) s_q[i] = d;
        }
    }
    __syncthreads();

    // ---- r[d] = sum_i q[i]*Wk[i,d], i split over halves, coalesced ----
    {
        int e = tid & 127, half = tid >> 7;
        const float* Kp = Wk + (size_t)half * 64 * DD + e;
        const float* qp = s_q + half * 64;
        float r = 0.f;
#pragma unroll 16
        for (int i = 0; i < 64; ++i)
            r += qp[i] * Kp[(size_t)i * DD];
        s_part[half * DD + e] = r;
    }
    __syncthreads();
    if (tid < DD) s_r[tid] = s_part[tid] + s_part[DD + tid];
    __syncthreads();

    // ---- pass 2 (L2): fused scores + online softmax + weighted sum ----
    // batch of 3 (12 xv regs) to fit the 51-reg budget at 5 CTAs/SM.
    const float scale = 0.08838834764831845f;  // 1/sqrt(128)
    {
        float4 rv = ((const float4*)s_r)[lane];
        float m = NEG_INF, Z = 0.f;
        float4 acc = make_float4(0.f, 0.f, 0.f, 0.f);
#pragma unroll
        for (int kb = 0; kb < 25; kb += 3) {
            const int nb = (25 - kb) < 3 ? (25 - kb) : 3;
            float4 xv[3];
            float  dt[3];
#pragma unroll
            for (int j = 0; j < 3; ++j)
                if (j < nb)
                    xv[j] = row4[(warp + (kb + j) * 8) * 32 + lane];
#pragma unroll
            for (int j = 0; j < 3; ++j)
                if (j < nb) {
                    float d = xv[j].x * rv.x + xv[j].y * rv.y +
                              xv[j].z * rv.z + xv[j].w * rv.w;
                    dt[j] = warp_sum(d);
                }
#pragma unroll
            for (int j = 0; j < 3; ++j)
                if (j < nb) {
                    int t = warp + (kb + j) * 8;
                    float dl = s_dlog[t];
                    if (dl != NEG_INF) {
                        float s = dt[j] * scale + dl;
                        if (s > m) {
                            float c = __expf(m - s);
                            Z *= c;
                            acc.x *= c; acc.y *= c; acc.z *= c; acc.w *= c;
                            m = s;
                        }
                        float p = __expf(s - m);
                        Z += p;
                        acc.x += p * xv[j].x; acc.y += p * xv[j].y;
                        acc.z += p * xv[j].z; acc.w += p * xv[j].w;
                    }
                }
        }
        ((float4*)s_part)[warp * 32 + lane] = acc;
        if (lane == 0) { s_wm[warp] = m; s_wz[warp] = Z; }
    }
    __syncthreads();

    // ---- merge warp states, write normalized w to global scratch ----
    if (tid < DD) {
        float M = s_wm[0];
#pragma unroll
        for (int j = 1; j < 8; ++j) M = fmaxf(M, s_wm[j]);
        float Zt = 0.f, w = 0.f;
#pragma unroll
        for (int j = 0; j < 8; ++j) {
            float f = __expf(s_wm[j] - M);
            Zt += f * s_wz[j];
            w  += f * s_part[j * DD + tid];
        }
        g_w[(size_t)b * DD + tid] = w / Zt;
    }

    // ---- short-term window (L2-hot rows), gate; write pre-gated parts ----
    if (tid < DD) {
        int cnt = (int)(cntf + 0.5f);
        if (cnt < 1) cnt = 1;
        int start = cnt - KS;
        if (start < 0) start = 0;
        float dn = (float)(cnt - start);

        float st = 0.f;
        for (int t = start; t < cnt; ++t) st += row[t * DD + tid];
        st /= dn;

        float mp = 0.f, mr = 0.f;
        for (int t = start; t < cnt; ++t) { mp += s_pop[t]; mr += s_age[t]; }
        mp /= dn; mr /= dn;

        float z = mp * gate_w[0] + mr * gate_w[1] + gate_b[0];
        float g = 1.f / (1.f + __expf(-z));
        g_us[(size_t)b * DD + tid] = g * st;
        if (tid == 0) g_omg[b] = 1.f - g;
    }
}

// combine v3: grid 256 x 16 rows, full Wv staged once per CTA (2 CTAs/SM),
// float4 LDS GEMM, gate-combine + LN.
__global__ void __launch_bounds__(CB_THREADS, 2)
combine_kernel(const float* __restrict__ Wv,
               const float* __restrict__ ln_g,
               const float* __restrict__ ln_b,
               float* __restrict__ out) {
    extern __shared__ float cs[];
    float4* wv4 = (float4*)cs;                     // [DD][WV_P4] float4s
    float*  w_s = cs + DD * WV_P4 * 4;             // [CB_ROWS][DD], reused for LT
    float4* w4s = (float4*)w_s;

    const int tid  = threadIdx.x;
    const int lane = tid & 31;
    const int warp = tid >> 5;                     // 0..7
    const int row0 = blockIdx.x * CB_ROWS;
    const int r0 = warp * 2;                       // 2 rows per warp

    // stage Wv: 4096 float4 over 256 threads = 16 iters
#pragma unroll
    for (int k = 0; k < 16; ++k) {
        int i = tid + k * CB_THREADS;
        int e = i >> 5, d4 = i & 31;
        wv4[e * WV_P4 + d4] = ((const float4*)Wv)[i];
    }
    // load w rows (16x128 = 512 float4) over 256 threads = 2 iters
#pragma unroll
    for (int k = 0; k < 2; ++k) {
        int i = tid + k * CB_THREADS;
        w4s[i] = ((const float4*)(g_w + (size_t)row0 * DD))[i];
    }
    __syncthreads();

    // GEMM: thread tile 2 rows x 4 e, float4 over d (32 iters)
    float acc[2][4] = {};
#pragma unroll 4
    for (int d4 = 0; d4 < 32; ++d4) {
        float4 wr[2], vv[4];
#pragma unroll
        for (int i = 0; i < 2; ++i) wr[i] = w4s[(r0 + i) * 32 + d4];
#pragma unroll
        for (int j = 0; j < 4; ++j) vv[j] = wv4[(lane + 32 * j) * WV_P4 + d4];
#pragma unroll
        for (int i = 0; i < 2; ++i)
#pragma unroll
            for (int j = 0; j < 4; ++j)
                acc[i][j] += wr[i].x * vv[j].x + wr[i].y * vv[j].y +
                             wr[i].z * vv[j].z + wr[i].w * vv[j].w;
    }
    __syncthreads();
    // store LT into w_s (w fully consumed)
#pragma unroll
    for (int i = 0; i < 2; ++i)
#pragma unroll
        for (int j = 0; j < 4; ++j)
            w_s[(r0 + i) * DD + lane + 32 * j] = acc[i][j];
    __syncthreads();

    // LN: 2 rows per warp
    const float4 lg4 = ((const float4*)ln_g)[lane];
    const float4 lb4 = ((const float4*)ln_b)[lane];
#pragma unroll
    for (int i = 0; i < 2; ++i) {
        int rr = r0 + i;
        int grow = row0 + rr;
        float4 lt4 = ((const float4*)(w_s + rr * DD))[lane];
        float4 us4 = ((const float4*)(g_us + (size_t)grow * DD))[lane];
        float om = g_omg[grow];
        float4 u;
        u.x = us4.x + om * lt4.x; u.y = us4.y + om * lt4.y;
        u.z = us4.z + om * lt4.z; u.w = us4.w + om * lt4.w;
        float mu = warp_sum(u.x + u.y + u.z + u.w) * (1.f / 128.f);
        float dx = u.x - mu, dy = u.y - mu, dz = u.z - mu, dw = u.w - mu;
        float var = warp_sum(dx * dx + dy * dy + dz * dz + dw * dw) * (1.f / 128.f);
        float rs = rsqrtf(var + 1e-5f);
        float4 o;
        o.x = dx * rs * lg4.x + lb4.x; o.y = dy * rs * lg4.y + lb4.y;
        o.z = dz * rs * lg4.z + lb4.z; o.w = dw * rs * lg4.w + lb4.w;
        ((float4*)(out + (size_t)grow * DD))[lane] = o;
    }
}

extern "C" void kernel_launch(void* const* d_in, const int* in_sizes, int n_in,
                              void* d_out, int out_size) {
    const float* items = (const float*)d_in[0];
    const int*   mask  = (const int*)d_in[1];
    const float* age   = (const float*)d_in[2];
    const float* pop   = (const float*)d_in[3];
    const float* Wq    = (const float*)d_in[4];
    const float* Wk    = (const float*)d_in[5];
    const float* Wv    = (const float*)d_in[6];
    const float* gw    = (const float*)d_in[7];
    const float* gb    = (const float*)d_in[8];
    const float* lng   = (const float*)d_in[9];
    const float* lnb   = (const float*)d_in[10];
    const float* da    = (const float*)d_in[11];
    float* out = (float*)d_out;

    user_enc_kernel<<<BB, NTHREADS>>>(items, mask, age, pop, Wq, Wk, gw, gb, da);
    cudaFuncSetAttribute(combine_kernel,
                         cudaFuncAttributeMaxDynamicSharedMemorySize, CB_SMEM);
    combine_kernel<<<BB / CB_ROWS, CB_THREADS, CB_SMEM>>>(Wv, lng, lnb, out);
}